// round 12
// baseline (speedup 1.0000x reference)
#include <cuda_runtime.h>
#include <cuda_fp16.h>
#include <cstdint>

// Router: logits = x@W + b (N=16384, D=2048, E=64), softmax, top-2, aux loss.
// fp16 m16n8k16 mma 3-pass (rn hi/lo split, residual scaled 2^12).
// Tiles pre-split into half2 smem (AH/AL/BH/BL) -> mainloop is pure LDS+MMA.
// Split accumulators + per-chunk drain of hh into FFMA fp32 sums.
// Output layout (float32): [weights N*2][indices-as-float N*2][aux 1]

#define DDIM   2048
#define EDIM   64
#define BM     128
#define BK     32
#define NCHUNK (DDIM / BK)      // 64
#define NTHREADS 256

#define APITCH 20               // u32 per A row (16 used) -> 20g+tg is bank-perm
#define BPITCH 20               // u32 per B row (16 used)

// u32-indexed tile layout inside the shared float array
#define AH_U   0                // 128 x 20 = 2560
#define AL_U   2560
#define BH_U   5120             // 64 x 20 = 1280
#define BL_U   6400             // -> 7680 u32 total
// float-indexed epilogue layout
#define LG_OFF    0             // reuse tile region: 128 x 65 = 8320
#define LG_STRIDE 65
#define BIAS_OFF  8320
#define CNT_OFF   8384
#define SMEM_FLOATS 8448        // 33792 bytes

#define RSCALE   4096.0f
#define RSCALE_I (1.0f / 4096.0f)

__device__ float g_cnt[EDIM];
__device__ float g_prob[EDIM];

__global__ void zero_acc_kernel() {
    int t = threadIdx.x;
    if (t < EDIM) { g_cnt[t] = 0.0f; g_prob[t] = 0.0f; }
}

__device__ __forceinline__ void mma16h(float d[4],
                                       uint32_t a0, uint32_t a1, uint32_t a2, uint32_t a3,
                                       uint32_t b0, uint32_t b1) {
    asm volatile(
        "mma.sync.aligned.m16n8k16.row.col.f32.f16.f16.f32 "
        "{%0,%1,%2,%3}, {%4,%5,%6,%7}, {%8,%9}, {%0,%1,%2,%3};"
        : "+f"(d[0]), "+f"(d[1]), "+f"(d[2]), "+f"(d[3])
        : "r"(a0), "r"(a1), "r"(a2), "r"(a3), "r"(b0), "r"(b1));
}

// (v0,v1) -> hi half2 (rn; low half = v0) and scaled-residual half2.
__device__ __forceinline__ void packsplit(float v0, float v1, uint32_t& hi, uint32_t& lo) {
    __half h0 = __float2half_rn(v0);
    __half h1 = __float2half_rn(v1);
    __half2 hp = __halves2half2(h0, h1);
    hi = *reinterpret_cast<uint32_t*>(&hp);
    float r0 = (v0 - __half2float(h0)) * RSCALE;
    float r1 = (v1 - __half2float(h1)) * RSCALE;
    __half2 lp = __floats2half2_rn(r0, r1);
    lo = *reinterpret_cast<uint32_t*>(&lp);
}

__global__ void __launch_bounds__(NTHREADS)
router_main_kernel(const float* __restrict__ x,
                   const float* __restrict__ W,
                   const float* __restrict__ b,
                   float* __restrict__ out, int N)
{
    __shared__ float sm[SMEM_FLOATS];
    uint32_t* su = reinterpret_cast<uint32_t*>(sm);
    const int tid  = threadIdx.x;
    const int lane = tid & 31;
    const int wid  = tid >> 5;          // 0..7
    const int wr   = wid >> 1;          // warp row 0..3: tokens [32*wr, +32)
    const int wc   = wid & 1;           // warp col 0..1: experts [32*wc, +32)
    const int g    = lane >> 2;         // 0..7
    const int tg   = lane & 3;          // 0..3
    const int row0 = blockIdx.x * BM;

    float sum[2][4][4];     // FFMA-maintained hh sums (unbiased)
    float acc[2][4][4];     // TC hh accumulator, drained each chunk
    float cor[2][4][4];     // TC correction accumulator (scaled by RSCALE)
    #pragma unroll
    for (int mf = 0; mf < 2; mf++)
        #pragma unroll
        for (int nf = 0; nf < 4; nf++)
            #pragma unroll
            for (int i = 0; i < 4; i++) {
                sum[mf][nf][i] = 0.0f; acc[mf][nf][i] = 0.0f; cor[mf][nf][i] = 0.0f;
            }

    // ---- prefetch chunk 0 ----
    // A: 128 rows x 8 float4; thread j-th piece: idx=tid+j*256, row=idx>>3, kq=(idx&7)*4
    // B: 1024 k-pairs; pp=tid+j*256, pair p=pp>>6, e=pp&63; loads W[2p][e], W[2p+1][e]
    float4 a4[4]; float bw0[4], bw1[4];
    {
        const float* xp = x + (size_t)row0 * DDIM;
        #pragma unroll
        for (int j = 0; j < 4; j++) {
            int idx = tid + j * NTHREADS;
            a4[j] = *(const float4*)(xp + (size_t)(idx >> 3) * DDIM + ((idx & 7) << 2));
        }
        #pragma unroll
        for (int j = 0; j < 4; j++) {
            int pp = tid + j * NTHREADS;
            int p = pp >> 6, e = pp & 63;
            bw0[j] = W[(size_t)(2 * p) * EDIM + e];
            bw1[j] = W[(size_t)(2 * p + 1) * EDIM + e];
        }
    }

    for (int c = 0; c < NCHUNK; c++) {
        // ---- split + store current chunk -> smem half2 tiles ----
        #pragma unroll
        for (int j = 0; j < 4; j++) {
            int idx = tid + j * NTHREADS;
            int row = idx >> 3;
            int pr  = (idx & 7) << 1;          // pair index (2 pairs per float4)
            uint32_t h0, l0, h1, l1;
            packsplit(a4[j].x, a4[j].y, h0, l0);
            packsplit(a4[j].z, a4[j].w, h1, l1);
            su[AH_U + row * APITCH + pr]     = h0;
            su[AH_U + row * APITCH + pr + 1] = h1;
            su[AL_U + row * APITCH + pr]     = l0;
            su[AL_U + row * APITCH + pr + 1] = l1;
        }
        #pragma unroll
        for (int j = 0; j < 4; j++) {
            int pp = tid + j * NTHREADS;
            int p = pp >> 6, e = pp & 63;
            uint32_t h, l;
            packsplit(bw0[j], bw1[j], h, l);
            su[BH_U + e * BPITCH + p] = h;
            su[BL_U + e * BPITCH + p] = l;
        }
        __syncthreads();

        // ---- issue global loads for chunk c+1 (overlap with MMAs) ----
        if (c + 1 < NCHUNK) {
            const int k0 = (c + 1) * BK;
            const float* xp = x + (size_t)row0 * DDIM + k0;
            #pragma unroll
            for (int j = 0; j < 4; j++) {
                int idx = tid + j * NTHREADS;
                a4[j] = *(const float4*)(xp + (size_t)(idx >> 3) * DDIM + ((idx & 7) << 2));
            }
            #pragma unroll
            for (int j = 0; j < 4; j++) {
                int pp = tid + j * NTHREADS;
                int p = pp >> 6, e = pp & 63;
                bw0[j] = W[(size_t)(k0 + 2 * p) * EDIM + e];
                bw1[j] = W[(size_t)(k0 + 2 * p + 1) * EDIM + e];
            }
        }

        // ---- compute chunk c: two k16 halves, pure LDS + MMA ----
        #pragma unroll
        for (int j = 0; j < 2; j++) {
            const int pb = (j << 3) + tg;      // pair base for this thread

            uint32_t bh[4][2], bl[4][2];
            #pragma unroll
            for (int nf = 0; nf < 4; nf++) {
                int e = (wc << 5) + (nf << 3) + g;
                bh[nf][0] = su[BH_U + e * BPITCH + pb];
                bh[nf][1] = su[BH_U + e * BPITCH + pb + 4];
                bl[nf][0] = su[BL_U + e * BPITCH + pb];
                bl[nf][1] = su[BL_U + e * BPITCH + pb + 4];
            }

            #pragma unroll
            for (int mf = 0; mf < 2; mf++) {
                int r0 = (wr << 5) + (mf << 4) + g;
                int r1 = r0 + 8;
                uint32_t ah0 = su[AH_U + r0 * APITCH + pb];
                uint32_t ah1 = su[AH_U + r1 * APITCH + pb];
                uint32_t ah2 = su[AH_U + r0 * APITCH + pb + 4];
                uint32_t ah3 = su[AH_U + r1 * APITCH + pb + 4];
                uint32_t al0 = su[AL_U + r0 * APITCH + pb];
                uint32_t al1 = su[AL_U + r1 * APITCH + pb];
                uint32_t al2 = su[AL_U + r0 * APITCH + pb + 4];
                uint32_t al3 = su[AL_U + r1 * APITCH + pb + 4];
                #pragma unroll
                for (int nf = 0; nf < 4; nf++) {
                    mma16h(acc[mf][nf], ah0, ah1, ah2, ah3, bh[nf][0], bh[nf][1]);
                    mma16h(cor[mf][nf], ah0, ah1, ah2, ah3, bl[nf][0], bl[nf][1]);
                    mma16h(cor[mf][nf], al0, al1, al2, al3, bh[nf][0], bh[nf][1]);
                }
            }
        }

        // ---- drain hh accumulator into FFMA sums ----
        #pragma unroll
        for (int mf = 0; mf < 2; mf++)
            #pragma unroll
            for (int nf = 0; nf < 4; nf++)
                #pragma unroll
                for (int i = 0; i < 4; i++) {
                    sum[mf][nf][i] += acc[mf][nf][i];
                    acc[mf][nf][i] = 0.0f;
                }

        __syncthreads();
    }

    // ---- bias/cnt init ----
    if (tid < EDIM) {
        sm[BIAS_OFF + tid] = b[tid];
        ((int*)sm)[CNT_OFF + tid] = 0;
    }

    // ---- spill logits (sum + unscaled correction) to smem ----
    {
        float* lg = sm + LG_OFF;
        #pragma unroll
        for (int mf = 0; mf < 2; mf++) {
            int t = (wr << 5) + (mf << 4) + g;
            #pragma unroll
            for (int nf = 0; nf < 4; nf++) {
                int e = (wc << 5) + (nf << 3) + (tg << 1);
                lg[t * LG_STRIDE + e]           = sum[mf][nf][0] + cor[mf][nf][0] * RSCALE_I;
                lg[t * LG_STRIDE + e + 1]       = sum[mf][nf][1] + cor[mf][nf][1] * RSCALE_I;
                lg[(t + 8) * LG_STRIDE + e]     = sum[mf][nf][2] + cor[mf][nf][2] * RSCALE_I;
                lg[(t + 8) * LG_STRIDE + e + 1] = sum[mf][nf][3] + cor[mf][nf][3] * RSCALE_I;
            }
        }
    }
    __syncthreads();

    // ---- per-token: bias + top-2 + softmax + outputs ----
    if (tid < BM) {
        const int m = tid;
        float lg[EDIM];
        #pragma unroll
        for (int e = 0; e < EDIM; e++)
            lg[e] = sm[LG_OFF + m * LG_STRIDE + e] + sm[BIAS_OFF + e];

        float v1 = -3.0e38f, v2 = -3.0e38f;
        int i1 = 0, i2 = 0;
        #pragma unroll
        for (int e = 0; e < EDIM; e++) {
            float l = lg[e];
            if (l > v1)      { v2 = v1; i2 = i1; v1 = l; i1 = e; }
            else if (l > v2) { v2 = l; i2 = e; }
        }
        float s = 0.0f;
        #pragma unroll
        for (int e = 0; e < EDIM; e++) s += __expf(lg[e] - v1);
        float inv = 1.0f / s;

        int gt = row0 + m;
        out[2 * gt + 0] = inv;
        out[2 * gt + 1] = __expf(v2 - v1) * inv;
        float* oi = out + 2 * (size_t)N;
        oi[2 * gt + 0] = (float)i1;
        oi[2 * gt + 1] = (float)i2;

        atomicAdd((int*)sm + CNT_OFF + i1, 1);
        atomicAdd((int*)sm + CNT_OFF + i2, 1);

        #pragma unroll
        for (int e = 0; e < EDIM; e++)
            sm[LG_OFF + m * LG_STRIDE + e] = __expf(lg[e] - v1) * inv;
    }
    __syncthreads();

    // ---- per-expert prob sums + global accumulation ----
    if (tid < EDIM) {
        float s = 0.0f;
        #pragma unroll 8
        for (int m = 0; m < BM; m++)
            s += sm[LG_OFF + m * LG_STRIDE + tid];
        atomicAdd(&g_prob[tid], s);
        atomicAdd(&g_cnt[tid], (float)(((int*)sm)[CNT_OFF + tid]));
    }
}

__global__ void finalize_kernel(float* __restrict__ out, int N) {
    __shared__ float red[64];
    int t = threadIdx.x;
    float invN = 1.0f / (float)N;
    red[t] = (g_cnt[t] * invN) * (g_prob[t] * invN);
    __syncthreads();
    if (t < 32) {
        float s = red[t] + red[t + 32];
        #pragma unroll
        for (int o = 16; o > 0; o >>= 1)
            s += __shfl_down_sync(0xffffffffu, s, o);
        if (t == 0) out[4 * (size_t)N] = (float)EDIM * s;
    }
}

extern "C" void kernel_launch(void* const* d_in, const int* in_sizes, int n_in,
                              void* d_out, int out_size) {
    const float* x = (const float*)d_in[0];
    const float* W = (const float*)d_in[1];
    const float* b = (const float*)d_in[2];
    int N = in_sizes[0] / DDIM;   // 16384

    float* out = (float*)d_out;
    zero_acc_kernel<<<1, 64>>>();
    router_main_kernel<<<N / BM, NTHREADS>>>(x, W, b, out, N);
    finalize_kernel<<<1, 64>>>(out, N);
}